// round 6
// baseline (speedup 1.0000x reference)
#include <cuda_runtime.h>

#define DIM    4096
#define RANK   32
#define NROWS  32          // B(4) * 8 edited rows
#define NDOTS  64          // per row: 32 src + 32 proj
#define NSPLIT 4           // K-dim split per dot
#define NCOPY  8192        // copy CTAs in the fused grid

// Partial dot products: [row j][dot di][split]
__device__ float g_part[NROWS * NDOTS * NSPLIT];

// ---------------------------------------------------------------------------
// Kernel A: one warp per (edited row j, dot di, K-split). 1024 CTAs.
// ---------------------------------------------------------------------------
__global__ __launch_bounds__(256) void dots_kernel(
    const float* __restrict__ hs,
    const float* __restrict__ Wsrc_p, const float* __restrict__ Wproj_p,
    const float* __restrict__ Wsrc_s, const float* __restrict__ Wproj_s,
    const int* __restrict__ offsets, const int* __restrict__ seqlens)
{
    const int warp = threadIdx.x >> 5;
    const int lane = threadIdx.x & 31;
    const int gw = blockIdx.x * 8 + warp;     // 0..8191
    const int j     = gw >> 8;                // 0..31
    const int di    = (gw >> 2) & 63;         // 0..63
    const int split = gw & 3;                 // 0..3

    const int b = j >> 3;
    const int slot = j & 7;
    int pos;
    const float *Wsrc, *Wproj;
    if (slot < 4) {
        pos = offsets[b] + slot;
        Wsrc = Wsrc_p; Wproj = Wproj_p;
    } else {
        pos = offsets[b] + seqlens[b] - 8 + slot;
        Wsrc = Wsrc_s; Wproj = Wproj_s;
    }

    const float4* x4 = (const float4*)(hs + ((long)b * 4096 + pos) * DIM);
    const float4* W4 = (const float4*)((di < RANK)
                           ? (Wsrc  + (long)di * DIM)
                           : (Wproj + (long)(di - RANK) * DIM));

    const int k0 = split * (DIM / 4 / NSPLIT);   // 256 float4 per split
    float acc = 0.f;
    #pragma unroll
    for (int k = 0; k < 8; k++) {
        const int i = k0 + lane + k * 32;
        float4 w  = W4[i];
        float4 xv = x4[i];
        acc += w.x * xv.x + w.y * xv.y + w.z * xv.z + w.w * xv.w;
    }
    #pragma unroll
    for (int o = 16; o > 0; o >>= 1)
        acc += __shfl_xor_sync(0xffffffff, acc, o);
    if (lane == 0) g_part[(j * NDOTS + di) * NSPLIT + split] = acc;
}

// ---------------------------------------------------------------------------
// Kernel B: NCOPY grid-stride copy CTAs (skip edited-row stores)
//           + 32 apply CTAs (bid >= NCOPY) that write the edited rows.
// ---------------------------------------------------------------------------
__global__ __launch_bounds__(256) void fused_kernel(
    const float* __restrict__ hs,
    const float* __restrict__ bsrc_p, const float* __restrict__ Wproj_p,
    const float* __restrict__ bsrc_s, const float* __restrict__ Wproj_s,
    const int* __restrict__ offsets, const int* __restrict__ seqlens,
    float* __restrict__ out)
{
    const int tid = threadIdx.x;

    if (blockIdx.x < NCOPY) {
        // ------- copy path: grid-stride over float4 elements -------
        __shared__ int ps[4];   // prefix start per batch
        __shared__ int ss[4];   // suffix start per batch
        if (tid < 4) {
            int o = offsets[tid];
            ps[tid] = o;
            ss[tid] = o + seqlens[tid] - 4;
        }
        __syncthreads();

        const float4* in4 = (const float4*)hs;
        float4*       o4  = (float4*)out;
        const long n4 = (long)NROWS / NROWS * (4L * 4096 * DIM / 4); // 16M
        long i = (long)blockIdx.x * 256 + tid;
        const long stride = (long)NCOPY * 256;
        for (; i < n4; i += stride) {
            const int row = (int)(i >> 10);       // i / (DIM/4)
            const int b = row >> 12;
            const int t = row & 4095;
            const bool edited = ((unsigned)(t - ps[b]) < 4u) |
                                ((unsigned)(t - ss[b]) < 4u);
            float4 v = in4[i];
            if (!edited) o4[i] = v;
        }
        return;
    }

    // ------- apply path: one CTA per edited row -------
    const int j = blockIdx.x - NCOPY;      // 0..31
    const int b = j >> 3;
    const int slot = j & 7;
    int pos;
    const float *bias, *Wproj;
    if (slot < 4) {
        pos = offsets[b] + slot;
        bias = bsrc_p; Wproj = Wproj_p;
    } else {
        pos = offsets[b] + seqlens[b] - 8 + slot;
        bias = bsrc_s; Wproj = Wproj_s;
    }

    __shared__ float s[RANK];
    if (tid < RANK) {
        const float* pp = &g_part[(j * NDOTS + tid) * NSPLIT];
        const float* qq = &g_part[(j * NDOTS + RANK + tid) * NSPLIT];
        float src  = pp[0] + pp[1] + pp[2] + pp[3] + bias[tid];
        float proj = qq[0] + qq[1] + qq[2] + qq[3];
        s[tid] = (src > 0.f ? src : 0.f) - proj;
    }
    __syncthreads();

    const long base = ((long)b * 4096 + pos) * DIM;
    const float4* x4 = (const float4*)(hs + base);
    float4*       o4 = (float4*)(out + base);
    #pragma unroll
    for (int k = 0; k < 4; k++) {
        int i = tid + k * 256;
        float4 acc = x4[i];
        #pragma unroll
        for (int r = 0; r < RANK; r++) {
            float4 w = ((const float4*)(Wproj + (long)r * DIM))[i];
            float sr = s[r];
            acc.x += sr * w.x;
            acc.y += sr * w.y;
            acc.z += sr * w.z;
            acc.w += sr * w.w;
        }
        o4[i] = acc;
    }
}

extern "C" void kernel_launch(void* const* d_in, const int* in_sizes, int n_in,
                              void* d_out, int out_size) {
    const float* hs      = (const float*)d_in[0];
    const float* Wsrc_p  = (const float*)d_in[1];
    const float* bsrc_p  = (const float*)d_in[2];
    const float* Wproj_p = (const float*)d_in[3];
    const float* Wsrc_s  = (const float*)d_in[4];
    const float* bsrc_s  = (const float*)d_in[5];
    const float* Wproj_s = (const float*)d_in[6];
    const int*   offsets = (const int*)d_in[7];
    const int*   seqlens = (const int*)d_in[8];
    float* out = (float*)d_out;

    dots_kernel<<<1024, 256>>>(hs, Wsrc_p, Wproj_p, Wsrc_s, Wproj_s,
                               offsets, seqlens);

    fused_kernel<<<NCOPY + NROWS, 256>>>(hs, bsrc_p, Wproj_p, bsrc_s, Wproj_s,
                                         offsets, seqlens, out);
}

// round 7
// speedup vs baseline: 1.1390x; 1.1390x over previous
#include <cuda_runtime.h>

#define DIM     4096
#define RANK    32
#define NEDIT   32          // B(4) * 8 edited rows
#define ROWS_PER_CTA 4
#define NCOPY   (16384 / ROWS_PER_CTA)   // 4096 copy CTAs

// asm-pinned vector load/store: volatile asm ops are never reordered w.r.t.
// each other, so 4 loads always issue before the 4 stores (MLP=4 guaranteed).
#define LDG4(v, p) asm volatile("ld.global.v4.f32 {%0,%1,%2,%3}, [%4];" \
    : "=f"((v).x), "=f"((v).y), "=f"((v).z), "=f"((v).w) : "l"(p))
#define STG4(p, v) asm volatile("st.global.v4.f32 [%0], {%1,%2,%3,%4};" \
    :: "l"(p), "f"((v).x), "f"((v).y), "f"((v).z), "f"((v).w) : "memory")

__global__ __launch_bounds__(256) void reft_mega_kernel(
    const float* __restrict__ hs,
    const float* __restrict__ Wsrc_p, const float* __restrict__ bsrc_p,
    const float* __restrict__ Wproj_p,
    const float* __restrict__ Wsrc_s, const float* __restrict__ bsrc_s,
    const float* __restrict__ Wproj_s,
    const int* __restrict__ offsets, const int* __restrict__ seqlens,
    float* __restrict__ out)
{
    const int tid = threadIdx.x;

    if (blockIdx.x >= NEDIT) {
        // =================== copy path: 4 contiguous rows ===================
        const int cbid = blockIdx.x - NEDIT;        // 0..4095
        // per-batch edited ranges (uniform, read once)
        int ps0 = offsets[0], ps1 = offsets[1], ps2 = offsets[2], ps3 = offsets[3];
        int ss0 = ps0 + seqlens[0] - 4, ss1 = ps1 + seqlens[1] - 4;
        int ss2 = ps2 + seqlens[2] - 4, ss3 = ps3 + seqlens[3] - 4;

        #pragma unroll
        for (int k = 0; k < ROWS_PER_CTA; k++) {
            const int row = cbid * ROWS_PER_CTA + k;
            const int b = row >> 12;
            const int t = row & 4095;
            const int ps = (b == 0) ? ps0 : (b == 1) ? ps1 : (b == 2) ? ps2 : ps3;
            const int ss = (b == 0) ? ss0 : (b == 1) ? ss1 : (b == 2) ? ss2 : ss3;
            if (((unsigned)(t - ps) < 4u) | ((unsigned)(t - ss) < 4u))
                continue;   // edited row: owned by an edit CTA

            const long base = (long)row * DIM;
            const float4* x4 = (const float4*)(hs + base);
            float4*       o4 = (float4*)(out + base);
            float4 v0, v1, v2, v3;
            LDG4(v0, x4 + tid);
            LDG4(v1, x4 + tid + 256);
            LDG4(v2, x4 + tid + 512);
            LDG4(v3, x4 + tid + 768);
            STG4(o4 + tid,       v0);
            STG4(o4 + tid + 256, v1);
            STG4(o4 + tid + 512, v2);
            STG4(o4 + tid + 768, v3);
        }
        return;
    }

    // =================== edit path: one CTA per edited row ===================
    const int j = blockIdx.x;        // 0..31
    const int b = j >> 3;
    const int slot = j & 7;
    int pos;
    const float *Wsrc, *bias, *Wproj;
    if (slot < 4) {
        pos = offsets[b] + slot;
        Wsrc = Wsrc_p; bias = bsrc_p; Wproj = Wproj_p;
    } else {
        pos = offsets[b] + seqlens[b] - 8 + slot;
        Wsrc = Wsrc_s; bias = bsrc_s; Wproj = Wproj_s;
    }

    __shared__ float4 xs4[DIM / 4];  // 16 KB
    __shared__ float  dots[2 * RANK];
    __shared__ float  s[RANK];

    const long base = ((long)b * 4096 + pos) * DIM;
    const float4* x4 = (const float4*)(hs + base);
    #pragma unroll
    for (int k = 0; k < 4; k++) {
        int i = tid + k * 256;
        xs4[i] = x4[i];
    }
    __syncthreads();

    // 64 dots: 8 warps x 8 dots, two accumulators to shorten FFMA chains
    const int warp = tid >> 5;
    const int lane = tid & 31;
    #pragma unroll
    for (int k = 0; k < 8; k++) {
        const int di = warp * 8 + k;       // 0..63
        const float4* W4 = (const float4*)((di < RANK)
                               ? (Wsrc  + (long)di * DIM)
                               : (Wproj + (long)(di - RANK) * DIM));
        float acc0 = 0.f, acc1 = 0.f;
        #pragma unroll 4
        for (int i = lane; i < DIM / 4; i += 64) {
            float4 w0 = W4[i],      xv0 = xs4[i];
            float4 w1 = W4[i + 32], xv1 = xs4[i + 32];
            acc0 += w0.x * xv0.x + w0.y * xv0.y + w0.z * xv0.z + w0.w * xv0.w;
            acc1 += w1.x * xv1.x + w1.y * xv1.y + w1.z * xv1.z + w1.w * xv1.w;
        }
        float acc = acc0 + acc1;
        #pragma unroll
        for (int o = 16; o > 0; o >>= 1)
            acc += __shfl_xor_sync(0xffffffff, acc, o);
        if (lane == 0) dots[di] = acc;
    }
    __syncthreads();

    if (tid < RANK) {
        float src  = dots[tid] + bias[tid];
        float proj = dots[tid + RANK];
        s[tid] = (src > 0.f ? src : 0.f) - proj;
    }
    __syncthreads();

    float4* o4 = (float4*)(out + base);
    #pragma unroll
    for (int k = 0; k < 4; k++) {
        int i = tid + k * 256;
        float4 acc = xs4[i];
        #pragma unroll
        for (int r = 0; r < RANK; r++) {
            float4 w = ((const float4*)(Wproj + (long)r * DIM))[i];
            float sr = s[r];
            acc.x += sr * w.x;
            acc.y += sr * w.y;
            acc.z += sr * w.z;
            acc.w += sr * w.w;
        }
        o4[i] = acc;
    }
}

extern "C" void kernel_launch(void* const* d_in, const int* in_sizes, int n_in,
                              void* d_out, int out_size) {
    const float* hs      = (const float*)d_in[0];
    const float* Wsrc_p  = (const float*)d_in[1];
    const float* bsrc_p  = (const float*)d_in[2];
    const float* Wproj_p = (const float*)d_in[3];
    const float* Wsrc_s  = (const float*)d_in[4];
    const float* bsrc_s  = (const float*)d_in[5];
    const float* Wproj_s = (const float*)d_in[6];
    const int*   offsets = (const int*)d_in[7];
    const int*   seqlens = (const int*)d_in[8];
    float* out = (float*)d_out;

    reft_mega_kernel<<<NEDIT + NCOPY, 256>>>(
        hs, Wsrc_p, bsrc_p, Wproj_p, Wsrc_s, bsrc_s, Wproj_s,
        offsets, seqlens, out);
}